// round 5
// baseline (speedup 1.0000x reference)
#include <cuda_runtime.h>
#include <cuda_fp16.h>

// B=8192, T=16, M=16, V=256 fixed.
#define INS_DEL 10.0f
#define FIRST_CHAR_COST 10.0f

#define WARPS_PER_BLOCK 4
#define THREADS_PER_BLOCK (WARPS_PER_BLOCK * 32)

// Per-warp shared: E[t][v] half (raw exp), row stride 264 halves (528B = 33
// granules -> ldmatrix conflict-free); S[t][m] fp32 stride 18.
#define PSTR 264
#define P_BYTES (16 * PSTR * 2)              // 8448
#define SSTRIDE 18
#define S_BYTES (16 * SSTRIDE * 4)           // 1152
#define WARP_SMEM_BYTES (P_BYTES + S_BYTES)  // 9600
#define SMEM_BYTES (WARPS_PER_BLOCK * WARP_SMEM_BYTES)

// fp16 copy of phon_cost, built once per run by a prologue kernel.
__device__ __half g_phon_h[256 * 256];

__global__ void cvt_phon_kernel(const float* __restrict__ phon) {
    const int i = blockIdx.x * blockDim.x + threadIdx.x;   // 16384 threads
    float4 v = ((const float4*)phon)[i];
    __half2 h0 = __floats2half2_rn(v.x, v.y);
    __half2 h1 = __floats2half2_rn(v.z, v.w);
    ((uint2*)g_phon_h)[i] = make_uint2(*(unsigned*)&h0, *(unsigned*)&h1);
}

__device__ __forceinline__ void ldsm_x4(unsigned &r0, unsigned &r1,
                                        unsigned &r2, unsigned &r3,
                                        unsigned saddr) {
    asm volatile("ldmatrix.sync.aligned.m8n8.x4.shared.b16 {%0,%1,%2,%3}, [%4];\n"
                 : "=r"(r0), "=r"(r1), "=r"(r2), "=r"(r3) : "r"(saddr));
}

__device__ __forceinline__ void mma16816(float d[4],
                                         unsigned a0, unsigned a1,
                                         unsigned a2, unsigned a3,
                                         unsigned b0, unsigned b1) {
    asm volatile("mma.sync.aligned.m16n8k16.row.col.f32.f16.f16.f32 "
                 "{%0,%1,%2,%3}, {%4,%5,%6,%7}, {%8,%9}, {%0,%1,%2,%3};\n"
                 : "+f"(d[0]), "+f"(d[1]), "+f"(d[2]), "+f"(d[3])
                 : "r"(a0), "r"(a1), "r"(a2), "r"(a3), "r"(b0), "r"(b1));
}

__device__ __forceinline__ unsigned pack_h2(float x, float y) {
    __half2 h = __floats2half2_rn(x, y);
    return *(unsigned*)&h;
}

__global__ void __launch_bounds__(THREADS_PER_BLOCK, 5)
rhyme_dp_kernel(const float* __restrict__ logits,
                const int* __restrict__ tgt,
                float* __restrict__ out, int B)
{
    extern __shared__ char smem[];
    const int w    = threadIdx.x >> 5;
    const int lane = threadIdx.x & 31;
    const int b    = blockIdx.x * WARPS_PER_BLOCK + w;
    if (b >= B) return;

    __half* E = (__half*)(smem + w * WARP_SMEM_BYTES);
    float*  S = (float*)(smem + w * WARP_SMEM_BYTES + P_BYTES);

    const float* lg = logits + (size_t)b * (16 * 256);
    const int m = lane & 15;

    const int gm = tgt[b * 16 + m];
    const int g0 = __shfl_sync(0xffffffffu, gm, 0);

    // -------- Phase 1: raw exp -> shared E (half). No reductions. ----------
    {
        const float4* rows = (const float4*)lg;   // 16 rows x 64 float4
        const int li = lane * 2;
#pragma unroll
        for (int t = 0; t < 16; ++t) {
            float4 x0 = rows[t * 64 + li];
            float4 x1 = rows[t * 64 + li + 1];
            unsigned h[4];
            h[0] = pack_h2(__expf(x0.x), __expf(x0.y));
            h[1] = pack_h2(__expf(x0.z), __expf(x0.w));
            h[2] = pack_h2(__expf(x1.x), __expf(x1.y));
            h[3] = pack_h2(__expf(x1.z), __expf(x1.w));
            *(uint4*)(E + t * PSTR + lane * 8) = *(uint4*)h;
        }
    }
    __syncwarp();

    // -------- Phase 2: [sub_raw | Z] = E @ [C_gather | ones] via HMMA -------
    // B fragments load directly from the fp16 phon table (L1-resident):
    // each aligned half-pair IS a b-register. Third n-tile = ones -> Z[t].
    float d0[4] = {0.f, 0.f, 0.f, 0.f};
    float d1[4] = {0.f, 0.f, 0.f, 0.f};
    float d2[4] = {0.f, 0.f, 0.f, 0.f};
    float z0_lane0;
    {
        unsigned pbase = (unsigned)__cvta_generic_to_shared(E);
        unsigned abase = pbase + (unsigned)((lane & 15) * (PSTR * 2) + (lane >> 4) * 16);

        const int gn0 = __shfl_sync(0xffffffffu, gm, lane >> 2);
        const int gn1 = __shfl_sync(0xffffffffu, gm, 8 + (lane >> 2));
        const __half* rh0 = g_phon_h + (size_t)gn0 * 256 + (lane & 3) * 2;
        const __half* rh1 = g_phon_h + (size_t)gn1 * 256 + (lane & 3) * 2;

        // ones-column B fragment: col n=0 -> lanes 0..3 hold 1.0 pairs
        const unsigned bone = (lane < 4) ? pack_h2(1.0f, 1.0f) : 0u;

#pragma unroll
        for (int kt = 0; kt < 16; ++kt) {
            unsigned a0, a1, a2, a3;
            ldsm_x4(a0, a1, a2, a3, abase + kt * 32);

            const unsigned b00 = __ldg((const unsigned*)(rh0 + kt * 16));
            const unsigned b01 = __ldg((const unsigned*)(rh0 + kt * 16 + 8));
            const unsigned b10 = __ldg((const unsigned*)(rh1 + kt * 16));
            const unsigned b11 = __ldg((const unsigned*)(rh1 + kt * 16 + 8));

            mma16816(d0, a0, a1, a2, a3, b00, b01);
            mma16816(d1, a0, a1, a2, a3, b10, b11);
            mma16816(d2, a0, a1, a2, a3, bone, bone);
        }

        // -------- writeback: S[t][m] = sub_raw / Z[t] -----------------------
        const float zlo = __shfl_sync(0xffffffffu, d2[0], lane & ~3);
        const float zhi = __shfl_sync(0xffffffffu, d2[2], lane & ~3);
        z0_lane0 = __shfl_sync(0xffffffffu, d2[0], 0);   // Z[0]
        const float rzlo = __fdividef(1.0f, zlo);
        const float rzhi = __fdividef(1.0f, zhi);

        const int tq = lane >> 2;
        const int mc = (lane & 3) * 2;
        *(float2*)(S + tq * SSTRIDE + mc)           = make_float2(d0[0] * rzlo, d0[1] * rzlo);
        *(float2*)(S + (tq + 8) * SSTRIDE + mc)     = make_float2(d0[2] * rzhi, d0[3] * rzhi);
        *(float2*)(S + tq * SSTRIDE + mc + 8)       = make_float2(d1[0] * rzlo, d1[1] * rzlo);
        *(float2*)(S + (tq + 8) * SSTRIDE + mc + 8) = make_float2(d1[2] * rzhi, d1[3] * rzhi);
    }
    __syncwarp();

    // -------- Phase 3: soft-DP wavefront (lane = column j-1) ----------------
    float cur = 0.0f, prev = 0.0f;
#pragma unroll
    for (int s = 0; s <= 30; ++s) {
        float leftv = __shfl_up_sync(0xffffffffu, cur, 1);
        float diagv = __shfl_up_sync(0xffffffffu, prev, 1);
        const int i = s - m + 1;
        const bool active = (i >= 1) && (i <= 16);

        float up;
        if (i == 1) {                 // row above is DP row 0: 10*j
            up    = INS_DEL * (float)(m + 1);
            diagv = INS_DEL * (float)m;
        } else {
            up = cur;
        }
        if (m == 0) {                 // column left is DP col 0: 10*i
            leftv = INS_DEL * (float)i;
            diagv = INS_DEL * (float)(i - 1);
        }

        const int si = active ? (s - m) : 0;
        const float sc = S[si * SSTRIDE + m];

        const float a  = up    + INS_DEL;
        const float bb = leftv + INS_DEL;
        const float c  = diagv + sc;
        const float mn = fminf(a, fminf(bb, c));
        const float r  = __expf(mn - a) + __expf(mn - bb) + __expf(mn - c);
        const float val = mn - __logf(r);

        if (active) { prev = cur; cur = val; }
    }

    // -------- Phase 4: first-char term + output -----------------------------
    if (lane == 15) {
        const float fm = __half2float(E[g0]) * __fdividef(1.0f, z0_lane0);
        out[b] = cur + FIRST_CHAR_COST * (1.0f - fm);
    }
}

extern "C" void kernel_launch(void* const* d_in, const int* in_sizes, int n_in,
                              void* d_out, int out_size)
{
    const float* logits = (const float*)d_in[0];   // tail_logits (B,T,V) f32
    const int*   tgt    = (const int*)  d_in[1];   // target_idx  (B,M) i32
    const float* phon   = (const float*)d_in[2];   // phon_cost   (V,V) f32
    float* out = (float*)d_out;
    const int B = out_size;                        // 8192

    // Prologue: fp32 -> fp16 phon table (64K elems, 4 per thread).
    cvt_phon_kernel<<<64, 256>>>(phon);

    cudaFuncSetAttribute(rhyme_dp_kernel,
                         cudaFuncAttributeMaxDynamicSharedMemorySize,
                         SMEM_BYTES);
    const int grid = (B + WARPS_PER_BLOCK - 1) / WARPS_PER_BLOCK;
    rhyme_dp_kernel<<<grid, THREADS_PER_BLOCK, SMEM_BYTES>>>(
        logits, tgt, out, B);
}

// round 6
// speedup vs baseline: 1.0980x; 1.0980x over previous
#include <cuda_runtime.h>
#include <cuda_fp16.h>

// B=8192, T=16, M=16, V=256 fixed.
#define INS_DEL 10.0f
#define FIRST_CHAR_COST 10.0f

#define WARPS_PER_BLOCK 4
#define THREADS_PER_BLOCK (WARPS_PER_BLOCK * 32)

// Per-warp shared: E[t][v] half (raw exp), row stride 264 halves (528B = 33
// granules -> ldmatrix conflict-free); S[t][m] = exp(-sub) fp32, stride 18.
#define PSTR 264
#define P_BYTES (16 * PSTR * 2)              // 8448
#define SSTRIDE 18
#define S_BYTES (16 * SSTRIDE * 4)           // 1152
#define WARP_SMEM_BYTES (P_BYTES + S_BYTES)  // 9600
#define SMEM_BYTES (WARPS_PER_BLOCK * WARP_SMEM_BYTES)

#define K10 4.5399929762484854e-05f          // e^{-10}

__device__ __forceinline__ void ldsm_x4(unsigned &r0, unsigned &r1,
                                        unsigned &r2, unsigned &r3,
                                        unsigned saddr) {
    asm volatile("ldmatrix.sync.aligned.m8n8.x4.shared.b16 {%0,%1,%2,%3}, [%4];\n"
                 : "=r"(r0), "=r"(r1), "=r"(r2), "=r"(r3) : "r"(saddr));
}

__device__ __forceinline__ void mma16816(float d[4],
                                         unsigned a0, unsigned a1,
                                         unsigned a2, unsigned a3,
                                         unsigned b0, unsigned b1) {
    asm volatile("mma.sync.aligned.m16n8k16.row.col.f32.f16.f16.f32 "
                 "{%0,%1,%2,%3}, {%4,%5,%6,%7}, {%8,%9}, {%0,%1,%2,%3};\n"
                 : "+f"(d[0]), "+f"(d[1]), "+f"(d[2]), "+f"(d[3])
                 : "r"(a0), "r"(a1), "r"(a2), "r"(a3), "r"(b0), "r"(b1));
}

__device__ __forceinline__ unsigned pack_h2(float x, float y) {
    __half2 h = __floats2half2_rn(x, y);
    return *(unsigned*)&h;
}

__global__ void __launch_bounds__(THREADS_PER_BLOCK, 5)
rhyme_dp_kernel(const float* __restrict__ logits,
                const int* __restrict__ tgt,
                const float* __restrict__ phon,
                float* __restrict__ out, int B)
{
    extern __shared__ char smem[];
    const int w    = threadIdx.x >> 5;
    const int lane = threadIdx.x & 31;
    const int b    = blockIdx.x * WARPS_PER_BLOCK + w;
    if (b >= B) return;

    __half* E = (__half*)(smem + w * WARP_SMEM_BYTES);
    float*  S = (float*)(smem + w * WARP_SMEM_BYTES + P_BYTES);

    const float* lg = logits + (size_t)b * (16 * 256);
    const int m = lane & 15;

    const int gm = tgt[b * 16 + m];
    const int g0 = __shfl_sync(0xffffffffu, gm, 0);

    // -------- Phase 1: raw exp -> shared E (half). No reductions. ----------
    {
        const float4* rows = (const float4*)lg;   // 16 rows x 64 float4
        const int li = lane * 2;
#pragma unroll
        for (int t = 0; t < 16; ++t) {
            float4 x0 = rows[t * 64 + li];
            float4 x1 = rows[t * 64 + li + 1];
            unsigned h[4];
            h[0] = pack_h2(__expf(x0.x), __expf(x0.y));
            h[1] = pack_h2(__expf(x0.z), __expf(x0.w));
            h[2] = pack_h2(__expf(x1.x), __expf(x1.y));
            h[3] = pack_h2(__expf(x1.z), __expf(x1.w));
            *(uint4*)(E + t * PSTR + lane * 8) = *(uint4*)h;
        }
    }
    __syncwarp();

    // -------- Phase 2: [sub_raw | Z] = E @ [C_gather | ones] via HMMA -------
    float d0[4] = {0.f, 0.f, 0.f, 0.f};
    float d1[4] = {0.f, 0.f, 0.f, 0.f};
    float d2[4] = {0.f, 0.f, 0.f, 0.f};
    float z0_lane0;
    {
        unsigned pbase = (unsigned)__cvta_generic_to_shared(E);
        unsigned abase = pbase + (unsigned)((lane & 15) * (PSTR * 2) + (lane >> 4) * 16);

        const int gn0 = __shfl_sync(0xffffffffu, gm, lane >> 2);
        const int gn1 = __shfl_sync(0xffffffffu, gm, 8 + (lane >> 2));
        const float* r0 = phon + (size_t)gn0 * 256 + (lane & 3) * 2;
        const float* r1 = phon + (size_t)gn1 * 256 + (lane & 3) * 2;

        const unsigned bone = (lane < 4) ? pack_h2(1.0f, 1.0f) : 0u;

#pragma unroll
        for (int kt = 0; kt < 16; ++kt) {
            unsigned a0, a1, a2, a3;
            ldsm_x4(a0, a1, a2, a3, abase + kt * 32);

            float2 f00 = __ldg((const float2*)(r0 + kt * 16));
            float2 f01 = __ldg((const float2*)(r0 + kt * 16 + 8));
            float2 f10 = __ldg((const float2*)(r1 + kt * 16));
            float2 f11 = __ldg((const float2*)(r1 + kt * 16 + 8));

            mma16816(d0, a0, a1, a2, a3, pack_h2(f00.x, f00.y), pack_h2(f01.x, f01.y));
            mma16816(d1, a0, a1, a2, a3, pack_h2(f10.x, f10.y), pack_h2(f11.x, f11.y));
            mma16816(d2, a0, a1, a2, a3, bone, bone);
        }

        // -------- writeback: S[t][m] = exp(-sub[t][m]) ----------------------
        const float zlo = __shfl_sync(0xffffffffu, d2[0], lane & ~3);
        const float zhi = __shfl_sync(0xffffffffu, d2[2], lane & ~3);
        z0_lane0 = __shfl_sync(0xffffffffu, d2[0], 0);   // Z[0]
        const float rzlo = -__fdividef(1.0f, zlo);
        const float rzhi = -__fdividef(1.0f, zhi);

        const int tq = lane >> 2;
        const int mc = (lane & 3) * 2;
        *(float2*)(S + tq * SSTRIDE + mc) =
            make_float2(__expf(d0[0] * rzlo), __expf(d0[1] * rzlo));
        *(float2*)(S + (tq + 8) * SSTRIDE + mc) =
            make_float2(__expf(d0[2] * rzhi), __expf(d0[3] * rzhi));
        *(float2*)(S + tq * SSTRIDE + mc + 8) =
            make_float2(__expf(d1[0] * rzlo), __expf(d1[1] * rzlo));
        *(float2*)(S + (tq + 8) * SSTRIDE + mc + 8) =
            make_float2(__expf(d1[2] * rzhi), __expf(d1[3] * rzhi));
    }
    __syncwarp();

    // -------- Phase 3: soft-DP wavefront in w-domain (w = exp(-dp)) --------
    // w(i,j) = e^-10 * (w_up + w_left) + w_diag * exp(-sub[i-1][j-1])
    // Boundary: w(0,j) = e^{-10j}, w(i,0) = e^{-10i} (underflow to 0 is
    // numerically negligible: those paths carry weight < e^{-87}).
    const float em1 = __expf(-10.0f * (float)(m + 1));   // w(0, m+1)
    const float em  = __expf(-10.0f * (float)m);         // w(0, m)
    float bl = K10;    // lane-0 running e^{-10*i}, i = s+1
    float bd = 1.0f;   // lane-0 running e^{-10*(i-1)}

    float cur = 0.0f, prev = 0.0f;
#pragma unroll
    for (int s = 0; s <= 30; ++s) {
        float leftv = __shfl_up_sync(0xffffffffu, cur, 1);
        float diagv = __shfl_up_sync(0xffffffffu, prev, 1);
        const int i = s - m + 1;
        const bool active = (i >= 1) && (i <= 16);

        float up = cur;
        if (i == 1) { up = em1; diagv = em; }
        if (m == 0) { leftv = bl; diagv = bd; }

        const int si = active ? (s - m) : 0;
        const float es = S[si * SSTRIDE + m];

        const float val = K10 * (up + leftv) + diagv * es;

        if (active) { prev = cur; cur = val; }
        bd = bl; bl *= K10;
    }

    // -------- Phase 4: final log + first-char term + output -----------------
    if (lane == 15) {
        const float fm = __half2float(E[g0]) * __fdividef(1.0f, z0_lane0);
        out[b] = -__logf(cur) + FIRST_CHAR_COST * (1.0f - fm);
    }
}

extern "C" void kernel_launch(void* const* d_in, const int* in_sizes, int n_in,
                              void* d_out, int out_size)
{
    const float* logits = (const float*)d_in[0];   // tail_logits (B,T,V) f32
    const int*   tgt    = (const int*)  d_in[1];   // target_idx  (B,M) i32
    const float* phon   = (const float*)d_in[2];   // phon_cost   (V,V) f32
    float* out = (float*)d_out;
    const int B = out_size;                        // 8192

    cudaFuncSetAttribute(rhyme_dp_kernel,
                         cudaFuncAttributeMaxDynamicSharedMemorySize,
                         SMEM_BYTES);
    const int grid = (B + WARPS_PER_BLOCK - 1) / WARPS_PER_BLOCK;
    rhyme_dp_kernel<<<grid, THREADS_PER_BLOCK, SMEM_BYTES>>>(
        logits, tgt, phon, out, B);
}